// round 4
// baseline (speedup 1.0000x reference)
#include <cuda_runtime.h>
#include <cstdint>

// Problem constants
#define Bq 4
#define LQ 3000
#define LKk 750
#define LKH 375          // keys per half
#define Cc 64
#define NHh 4
#define Ff 256
#define RQ (Bq*LQ)       // 12000
#define RK (Bq*LKk)      // 3000
#define NQH (Bq*NHh*LQ)  // 48000 (b,h,q) rows

// ---------------- scratch (static device globals) --------------------------
static __device__ float g_qp [RQ*Cc];
static __device__ float g_kp [RK*Cc];
static __device__ float g_vp [RK*Cc];
static __device__ float g_att[RQ*Cc];
static __device__ float g_x  [RQ*Cc];
static __device__ float g_h1 [RQ*Ff];
static __device__ float g_x2 [RQ*Cc];
static __device__ float g_qnA[RQ*Cc];
static __device__ float g_qnB[RQ*Cc];
static __device__ float g_sg [RQ*Cc];
static __device__ float g_xn [RQ*Cc];
// plain-attention partials
static __device__ float g_pm [NQH*2];
static __device__ float g_pl [NQH*2];
static __device__ float g_po [NQH*2*16];

// ---------------- generic projection GEMM -----------------------------------
template<int K, int N, int RPT, int ACT>
__global__ __launch_bounds__(256)
void proj_kernel(const float* __restrict__ X, const float* __restrict__ W,
                 const float* __restrict__ bias, float* __restrict__ Y, int rows)
{
    extern __shared__ float4 Ws[];               // K * N/4 float4
    constexpr int C4 = N / 4;
    constexpr int RT = 256 / C4;
    for (int i = threadIdx.x; i < K * C4; i += 256)
        Ws[i] = reinterpret_cast<const float4*>(W)[i];
    __syncthreads();

    const int c4 = threadIdx.x & (C4 - 1);
    const int rt = threadIdx.x / C4;
    const int base = blockIdx.x * (RT * RPT);

    float4 acc[RPT];
    const float4* xr[RPT];
    int  rowv[RPT];
    bool valid[RPT];
#pragma unroll
    for (int i = 0; i < RPT; i++) {
        acc[i] = make_float4(0.f, 0.f, 0.f, 0.f);
        int r = base + rt + i * RT;
        valid[i] = r < rows;
        rowv[i] = r;
        xr[i] = reinterpret_cast<const float4*>(X + (size_t)(valid[i] ? r : 0) * K);
    }
#pragma unroll
    for (int k4 = 0; k4 < K / 4; k4++) {
        float4 xq[RPT];
#pragma unroll
        for (int i = 0; i < RPT; i++) xq[i] = __ldg(&xr[i][k4]);
        float4 w0 = Ws[(k4*4+0)*C4 + c4];
        float4 w1 = Ws[(k4*4+1)*C4 + c4];
        float4 w2 = Ws[(k4*4+2)*C4 + c4];
        float4 w3 = Ws[(k4*4+3)*C4 + c4];
#pragma unroll
        for (int i = 0; i < RPT; i++) {
            acc[i].x += xq[i].x*w0.x + xq[i].y*w1.x + xq[i].z*w2.x + xq[i].w*w3.x;
            acc[i].y += xq[i].x*w0.y + xq[i].y*w1.y + xq[i].z*w2.y + xq[i].w*w3.y;
            acc[i].z += xq[i].x*w0.z + xq[i].y*w1.z + xq[i].z*w2.z + xq[i].w*w3.z;
            acc[i].w += xq[i].x*w0.w + xq[i].y*w1.w + xq[i].z*w2.w + xq[i].w*w3.w;
        }
    }
#pragma unroll
    for (int i = 0; i < RPT; i++) {
        if (!valid[i]) continue;
        float4 o = acc[i];
        if (bias) {
            float4 bv = __ldg(&reinterpret_cast<const float4*>(bias)[c4]);
            o.x += bv.x; o.y += bv.y; o.z += bv.z; o.w += bv.w;
        }
        if (ACT == 1) {
            o.x = fmaxf(o.x, 0.f); o.y = fmaxf(o.y, 0.f);
            o.z = fmaxf(o.z, 0.f); o.w = fmaxf(o.w, 0.f);
        }
        reinterpret_cast<float4*>(Y + (size_t)rowv[i] * N)[c4] = o;
    }
}

// ---------------- dual-weight GEMM (K=64, N=64 each) ------------------------
// MODE 0: Y1 = X@Wa, Y2 = X@Wb      MODE 1: Y1 = sigmoid(X@Wa+ba)*(X@Wb+bb)
template<int MODE, int RPT>
__global__ __launch_bounds__(256)
void dual_kernel(const float* __restrict__ X,
                 const float* __restrict__ Wa, const float* __restrict__ Wb,
                 const float* __restrict__ ba, const float* __restrict__ bb,
                 float* __restrict__ Y1, float* __restrict__ Y2, int rows)
{
    __shared__ float4 Wsa[64*16];
    __shared__ float4 Wsb[64*16];
    for (int i = threadIdx.x; i < 64*16; i += 256) {
        Wsa[i] = reinterpret_cast<const float4*>(Wa)[i];
        Wsb[i] = reinterpret_cast<const float4*>(Wb)[i];
    }
    __syncthreads();
    const int c4 = threadIdx.x & 15;
    const int rt = threadIdx.x >> 4;
    const int base = blockIdx.x * (16 * RPT);

    float4 aacc[RPT], bacc[RPT];
    const float4* xr[RPT];
    int rowv[RPT]; bool valid[RPT];
#pragma unroll
    for (int i = 0; i < RPT; i++) {
        aacc[i] = make_float4(0,0,0,0); bacc[i] = make_float4(0,0,0,0);
        int r = base + rt + i * 16;
        valid[i] = r < rows; rowv[i] = r;
        xr[i] = reinterpret_cast<const float4*>(X + (size_t)(valid[i] ? r : 0) * 64);
    }
#pragma unroll
    for (int k4 = 0; k4 < 16; k4++) {
        float4 xq[RPT];
#pragma unroll
        for (int i = 0; i < RPT; i++) xq[i] = __ldg(&xr[i][k4]);
        float4 wa0 = Wsa[(k4*4+0)*16+c4], wa1 = Wsa[(k4*4+1)*16+c4];
        float4 wa2 = Wsa[(k4*4+2)*16+c4], wa3 = Wsa[(k4*4+3)*16+c4];
        float4 wb0 = Wsb[(k4*4+0)*16+c4], wb1 = Wsb[(k4*4+1)*16+c4];
        float4 wb2 = Wsb[(k4*4+2)*16+c4], wb3 = Wsb[(k4*4+3)*16+c4];
#pragma unroll
        for (int i = 0; i < RPT; i++) {
            aacc[i].x += xq[i].x*wa0.x + xq[i].y*wa1.x + xq[i].z*wa2.x + xq[i].w*wa3.x;
            aacc[i].y += xq[i].x*wa0.y + xq[i].y*wa1.y + xq[i].z*wa2.y + xq[i].w*wa3.y;
            aacc[i].z += xq[i].x*wa0.z + xq[i].y*wa1.z + xq[i].z*wa2.z + xq[i].w*wa3.z;
            aacc[i].w += xq[i].x*wa0.w + xq[i].y*wa1.w + xq[i].z*wa2.w + xq[i].w*wa3.w;
            bacc[i].x += xq[i].x*wb0.x + xq[i].y*wb1.x + xq[i].z*wb2.x + xq[i].w*wb3.x;
            bacc[i].y += xq[i].x*wb0.y + xq[i].y*wb1.y + xq[i].z*wb2.y + xq[i].w*wb3.y;
            bacc[i].z += xq[i].x*wb0.z + xq[i].y*wb1.z + xq[i].z*wb2.z + xq[i].w*wb3.z;
            bacc[i].w += xq[i].x*wb0.w + xq[i].y*wb1.w + xq[i].z*wb2.w + xq[i].w*wb3.w;
        }
    }
#pragma unroll
    for (int i = 0; i < RPT; i++) {
        if (!valid[i]) continue;
        if (MODE == 0) {
            reinterpret_cast<float4*>(Y1 + (size_t)rowv[i]*64)[c4] = aacc[i];
            reinterpret_cast<float4*>(Y2 + (size_t)rowv[i]*64)[c4] = bacc[i];
        } else {
            float4 bav = __ldg(&reinterpret_cast<const float4*>(ba)[c4]);
            float4 bbv = __ldg(&reinterpret_cast<const float4*>(bb)[c4]);
            float4 o;
            o.x = (bacc[i].x + bbv.x) / (1.f + __expf(-(aacc[i].x + bav.x)));
            o.y = (bacc[i].y + bbv.y) / (1.f + __expf(-(aacc[i].y + bav.y)));
            o.z = (bacc[i].z + bbv.z) / (1.f + __expf(-(aacc[i].z + bav.z)));
            o.w = (bacc[i].w + bbv.w) / (1.f + __expf(-(aacc[i].w + bav.w)));
            reinterpret_cast<float4*>(Y1 + (size_t)rowv[i]*64)[c4] = o;
        }
    }
}

// ---------------- GEMM + residual + LN (+GLU) (+LN2) (+head) ----------------
template<int K>
__global__ __launch_bounds__(256)
void gemm_ln_kernel(const float* __restrict__ X, const float* __restrict__ W,
                    const float* __restrict__ res, const float* __restrict__ bias,
                    const float* __restrict__ g, const float* __restrict__ be,
                    const float* __restrict__ qn, const float* __restrict__ sgv,
                    const float* __restrict__ g2, const float* __restrict__ b2,
                    const float* __restrict__ fw, const float* __restrict__ fb,
                    float* __restrict__ Y, float* __restrict__ Y2,
                    float* __restrict__ headout, int rows)
{
    extern __shared__ float4 Ws[];               // K*16 float4
    for (int i = threadIdx.x; i < K * 16; i += 256)
        Ws[i] = reinterpret_cast<const float4*>(W)[i];
    __syncthreads();

    const int c4 = threadIdx.x & 15;
    const int rt = threadIdx.x >> 4;
    const int base = blockIdx.x * 32;

    float4 acc[2];
    const float4* xr[2];
    int rowv[2];
#pragma unroll
    for (int i = 0; i < 2; i++) {
        acc[i] = make_float4(0,0,0,0);
        rowv[i] = base + rt + i * 16;             // rows always == RQ (exact)
        xr[i] = reinterpret_cast<const float4*>(X + (size_t)rowv[i] * K);
    }
#pragma unroll
    for (int k4 = 0; k4 < K / 4; k4++) {
        float4 xq[2];
#pragma unroll
        for (int i = 0; i < 2; i++) xq[i] = __ldg(&xr[i][k4]);
        float4 w0 = Ws[(k4*4+0)*16 + c4];
        float4 w1 = Ws[(k4*4+1)*16 + c4];
        float4 w2 = Ws[(k4*4+2)*16 + c4];
        float4 w3 = Ws[(k4*4+3)*16 + c4];
#pragma unroll
        for (int i = 0; i < 2; i++) {
            acc[i].x += xq[i].x*w0.x + xq[i].y*w1.x + xq[i].z*w2.x + xq[i].w*w3.x;
            acc[i].y += xq[i].x*w0.y + xq[i].y*w1.y + xq[i].z*w2.y + xq[i].w*w3.y;
            acc[i].z += xq[i].x*w0.z + xq[i].y*w1.z + xq[i].z*w2.z + xq[i].w*w3.z;
            acc[i].w += xq[i].x*w0.w + xq[i].y*w1.w + xq[i].z*w2.w + xq[i].w*w3.w;
        }
    }
    float4 gv = __ldg(&reinterpret_cast<const float4*>(g)[c4]);
    float4 bv = __ldg(&reinterpret_cast<const float4*>(be)[c4]);
#pragma unroll
    for (int i = 0; i < 2; i++) {
        int row = rowv[i];
        float4 o = acc[i];
        if (bias) {
            float4 b4 = __ldg(&reinterpret_cast<const float4*>(bias)[c4]);
            o.x += b4.x; o.y += b4.y; o.z += b4.z; o.w += b4.w;
        }
        float4 rv = reinterpret_cast<const float4*>(res + (size_t)row * 64)[c4];
        o.x += rv.x; o.y += rv.y; o.z += rv.z; o.w += rv.w;
        float s  = o.x + o.y + o.z + o.w;
        float ss = o.x*o.x + o.y*o.y + o.z*o.z + o.w*o.w;
#pragma unroll
        for (int off = 1; off < 16; off <<= 1) {
            s  += __shfl_xor_sync(0xffffffffu, s,  off);
            ss += __shfl_xor_sync(0xffffffffu, ss, off);
        }
        float mean = s * (1.f/64.f);
        float rstd = rsqrtf(ss * (1.f/64.f) - mean * mean + 1e-6f);
        o.x = (o.x - mean) * rstd * gv.x + bv.x;
        o.y = (o.y - mean) * rstd * gv.y + bv.y;
        o.z = (o.z - mean) * rstd * gv.z + bv.z;
        o.w = (o.w - mean) * rstd * gv.w + bv.w;
        if (qn) {
            float4 qv = reinterpret_cast<const float4*>(qn  + (size_t)row * 64)[c4];
            float4 sv = reinterpret_cast<const float4*>(sgv + (size_t)row * 64)[c4];
            o.x = qv.x + sv.x / (1.f + __expf(-o.x));
            o.y = qv.y + sv.y / (1.f + __expf(-o.y));
            o.z = qv.z + sv.z / (1.f + __expf(-o.z));
            o.w = qv.w + sv.w / (1.f + __expf(-o.w));
        }
        reinterpret_cast<float4*>(Y + (size_t)row * 64)[c4] = o;
        if (g2) {
            float s2  = o.x + o.y + o.z + o.w;
            float ss2 = o.x*o.x + o.y*o.y + o.z*o.z + o.w*o.w;
#pragma unroll
            for (int off = 1; off < 16; off <<= 1) {
                s2  += __shfl_xor_sync(0xffffffffu, s2,  off);
                ss2 += __shfl_xor_sync(0xffffffffu, ss2, off);
            }
            float mean2 = s2 * (1.f/64.f);
            float rstd2 = rsqrtf(ss2 * (1.f/64.f) - mean2 * mean2 + 1e-6f);
            float4 g2v = __ldg(&reinterpret_cast<const float4*>(g2)[c4]);
            float4 b2v = __ldg(&reinterpret_cast<const float4*>(b2)[c4]);
            float4 y2;
            y2.x = (o.x - mean2) * rstd2 * g2v.x + b2v.x;
            y2.y = (o.y - mean2) * rstd2 * g2v.y + b2v.y;
            y2.z = (o.z - mean2) * rstd2 * g2v.z + b2v.z;
            y2.w = (o.w - mean2) * rstd2 * g2v.w + b2v.w;
            reinterpret_cast<float4*>(Y2 + (size_t)row * 64)[c4] = y2;
        }
        if (fw) {
            float4 wv = __ldg(&reinterpret_cast<const float4*>(fw)[c4]);
            float d = o.x*wv.x + o.y*wv.y + o.z*wv.z + o.w*wv.w;
#pragma unroll
            for (int off = 1; off < 16; off <<= 1)
                d += __shfl_xor_sync(0xffffffffu, d, off);
            if (c4 == 0)
                headout[row] = 1.f / (1.f + __expf(-(d + __ldg(fb))));
        }
    }
}

// ---- Wo GEMM with inline plain-softmax combine (X from pm/pl/po) + LN ------
__global__ __launch_bounds__(256)
void gemm_ln_attn_kernel(const float* __restrict__ pm, const float* __restrict__ pl,
                         const float* __restrict__ po,
                         const float* __restrict__ W,
                         const float* __restrict__ res,
                         const float* __restrict__ g, const float* __restrict__ be,
                         float* __restrict__ Y)
{
    __shared__ float4 Ws[64*16];
    for (int i = threadIdx.x; i < 64*16; i += 256)
        Ws[i] = reinterpret_cast<const float4*>(W)[i];
    __syncthreads();

    const int c4 = threadIdx.x & 15;
    const int rt = threadIdx.x >> 4;
    const int base = blockIdx.x * 32;

    float4 acc[2];
    int rowv[2];
#pragma unroll
    for (int i = 0; i < 2; i++) { acc[i] = make_float4(0,0,0,0); rowv[i] = base + rt + i*16; }

#pragma unroll
    for (int i = 0; i < 2; i++) {
        int row = rowv[i];
        int b = row / LQ, qq = row - b * LQ;
#pragma unroll
        for (int h = 0; h < 4; h++) {
            size_t qidx = ((size_t)(b*4 + h)) * LQ + qq;
            float m0 = __ldg(&pm[qidx*2]),  m1 = __ldg(&pm[qidx*2+1]);
            float l0 = __ldg(&pl[qidx*2]),  l1 = __ldg(&pl[qidx*2+1]);
            float mm = fmaxf(m0, m1);
            float e0 = __expf(m0 - mm), e1 = __expf(m1 - mm);
            float inv = 1.f / (l0*e0 + l1*e1);
            e0 *= inv; e1 *= inv;
            const float4* pa = reinterpret_cast<const float4*>(po + qidx*32);
#pragma unroll
            for (int kk = 0; kk < 4; kk++) {
                float4 a = __ldg(&pa[kk]);
                float4 c = __ldg(&pa[kk + 4]);
                float4 xq;
                xq.x = a.x*e0 + c.x*e1; xq.y = a.y*e0 + c.y*e1;
                xq.z = a.z*e0 + c.z*e1; xq.w = a.w*e0 + c.w*e1;
                int k4 = h*4 + kk;
                float4 w0 = Ws[(k4*4+0)*16 + c4];
                float4 w1 = Ws[(k4*4+1)*16 + c4];
                float4 w2 = Ws[(k4*4+2)*16 + c4];
                float4 w3 = Ws[(k4*4+3)*16 + c4];
                acc[i].x += xq.x*w0.x + xq.y*w1.x + xq.z*w2.x + xq.w*w3.x;
                acc[i].y += xq.x*w0.y + xq.y*w1.y + xq.z*w2.y + xq.w*w3.y;
                acc[i].z += xq.x*w0.z + xq.y*w1.z + xq.z*w2.z + xq.w*w3.z;
                acc[i].w += xq.x*w0.w + xq.y*w1.w + xq.z*w2.w + xq.w*w3.w;
            }
        }
    }
    float4 gv = __ldg(&reinterpret_cast<const float4*>(g)[c4]);
    float4 bv = __ldg(&reinterpret_cast<const float4*>(be)[c4]);
#pragma unroll
    for (int i = 0; i < 2; i++) {
        int row = rowv[i];
        float4 o = acc[i];
        float4 rv = reinterpret_cast<const float4*>(res + (size_t)row * 64)[c4];
        o.x += rv.x; o.y += rv.y; o.z += rv.z; o.w += rv.w;
        float s  = o.x + o.y + o.z + o.w;
        float ss = o.x*o.x + o.y*o.y + o.z*o.z + o.w*o.w;
#pragma unroll
        for (int off = 1; off < 16; off <<= 1) {
            s  += __shfl_xor_sync(0xffffffffu, s,  off);
            ss += __shfl_xor_sync(0xffffffffu, ss, off);
        }
        float mean = s * (1.f/64.f);
        float rstd = rsqrtf(ss * (1.f/64.f) - mean * mean + 1e-6f);
        o.x = (o.x - mean) * rstd * gv.x + bv.x;
        o.y = (o.y - mean) * rstd * gv.y + bv.y;
        o.z = (o.z - mean) * rstd * gv.z + bv.z;
        o.w = (o.w - mean) * rstd * gv.w + bv.w;
        reinterpret_cast<float4*>(Y + (size_t)row * 64)[c4] = o;
    }
}

// ---------------- plain attention, split-K half: partial (m,l,o) ------------
__global__ __launch_bounds__(256, 3)
void attn_plain_part(const float* __restrict__ qp, const float* __restrict__ kp,
                     const float* __restrict__ vp,
                     float* __restrict__ pm, float* __restrict__ pl,
                     float* __restrict__ po)
{
    extern __shared__ float4 sKV[];  // [0,1500): K half, [1500,3000): V half
    const int bh = blockIdx.y >> 1, half = blockIdx.y & 1;
    const int b = bh >> 2, h = bh & 3;
    const int j0 = half * LKH;
    const float* kb = kp + ((size_t)(b * LKk + j0)) * Cc + h * 16;
    const float* vb = vp + ((size_t)(b * LKk + j0)) * Cc + h * 16;
    for (int idx = threadIdx.x; idx < LKH * 4; idx += 256) {
        int j = idx >> 2, d = idx & 3;
        sKV[idx]           = *reinterpret_cast<const float4*>(kb + (size_t)j * Cc + d * 4);
        sKV[idx + LKH * 4] = *reinterpret_cast<const float4*>(vb + (size_t)j * Cc + d * 4);
    }
    __syncthreads();

    int qi = blockIdx.x * 256 + threadIdx.x;
    if (qi >= LQ) return;
    const float* qr = qp + ((size_t)(b * LQ + qi)) * Cc + h * 16;
    float4 q0 = *reinterpret_cast<const float4*>(qr + 0);
    float4 q1 = *reinterpret_cast<const float4*>(qr + 4);
    float4 q2 = *reinterpret_cast<const float4*>(qr + 8);
    float4 q3 = *reinterpret_cast<const float4*>(qr + 12);
    const float sc = 0.25f;
    q0.x*=sc;q0.y*=sc;q0.z*=sc;q0.w*=sc; q1.x*=sc;q1.y*=sc;q1.z*=sc;q1.w*=sc;
    q2.x*=sc;q2.y*=sc;q2.z*=sc;q2.w*=sc; q3.x*=sc;q3.y*=sc;q3.z*=sc;q3.w*=sc;

    float m = -3.4e38f, l = 0.f;
    float4 o0 = {0,0,0,0}, o1v = {0,0,0,0}, o2 = {0,0,0,0}, o3 = {0,0,0,0};
    for (int j = 0; j < LKH; j++) {
        const float4* kj = &sKV[j * 4];
        float4 k0 = kj[0], k1 = kj[1], k2 = kj[2], k3 = kj[3];
        float s = q0.x*k0.x + q0.y*k0.y + q0.z*k0.z + q0.w*k0.w
                + q1.x*k1.x + q1.y*k1.y + q1.z*k1.z + q1.w*k1.w
                + q2.x*k2.x + q2.y*k2.y + q2.z*k2.z + q2.w*k2.w
                + q3.x*k3.x + q3.y*k3.y + q3.z*k3.z + q3.w*k3.w;
        float p;
        if (s > m) {
            float r = __expf(m - s);
            l *= r;
            o0.x*=r;o0.y*=r;o0.z*=r;o0.w*=r; o1v.x*=r;o1v.y*=r;o1v.z*=r;o1v.w*=r;
            o2.x*=r;o2.y*=r;o2.z*=r;o2.w*=r; o3.x*=r;o3.y*=r;o3.z*=r;o3.w*=r;
            m = s; p = 1.f;
        } else {
            p = __expf(s - m);
        }
        l += p;
        const float4* vj = &sKV[LKH*4 + j*4];
        float4 v0 = vj[0], v1 = vj[1], v2 = vj[2], v3 = vj[3];
        o0.x += p*v0.x; o0.y += p*v0.y; o0.z += p*v0.z; o0.w += p*v0.w;
        o1v.x += p*v1.x; o1v.y += p*v1.y; o1v.z += p*v1.z; o1v.w += p*v1.w;
        o2.x += p*v2.x; o2.y += p*v2.y; o2.z += p*v2.z; o2.w += p*v2.w;
        o3.x += p*v3.x; o3.y += p*v3.y; o3.z += p*v3.z; o3.w += p*v3.w;
    }
    size_t idx = (size_t)bh * LQ + qi;
    pm[idx*2 + half] = m;
    pl[idx*2 + half] = l;
    float4* pov = reinterpret_cast<float4*>(po + (idx*2 + half) * 16);
    pov[0] = o0; pov[1] = o1v; pov[2] = o2; pov[3] = o3;
}

// ---------------- AWG top-16 attention, fully fused --------------------------
// 2 threads per query (even lane: keys [0,375), odd lane: [375,750)).
// Pass 1: per-thread branch-free top-16 merge; pair-exact 16th largest via
//         shuffle bitonic selection. Pass 2: gated rescan (K in smem, V via
//         L2), pair-combined and written directly to att.
__global__ __launch_bounds__(256, 3)
void attn_topk_fused(const float* __restrict__ qp, const float* __restrict__ kp,
                     const float* __restrict__ vp, float* __restrict__ att)
{
    extern __shared__ float4 sK[];   // 750*4 float4 = 48 KB
    const int bh = blockIdx.y;
    const int b = bh >> 2, h = bh & 3;
    const float* kb = kp + ((size_t)b * LKk) * Cc + h * 16;
    const float* vb = vp + ((size_t)b * LKk) * Cc + h * 16;
    for (int idx = threadIdx.x; idx < LKk * 4; idx += 256) {
        int j = idx >> 2, d = idx & 3;
        sK[idx] = *reinterpret_cast<const float4*>(kb + (size_t)j * Cc + d * 4);
    }
    __syncthreads();

    const int tid = threadIdx.x;
    const int qi0 = blockIdx.x * 128 + (tid >> 1);
    const int qi  = qi0 < LQ ? qi0 : LQ - 1;       // clamp; keep all lanes live
    const int half = tid & 1;
    const int j0 = half * LKH;

    const float* qr = qp + ((size_t)(b * LQ + qi)) * Cc + h * 16;
    float4 q0 = *reinterpret_cast<const float4*>(qr + 0);
    float4 q1 = *reinterpret_cast<const float4*>(qr + 4);
    float4 q2 = *reinterpret_cast<const float4*>(qr + 8);
    float4 q3 = *reinterpret_cast<const float4*>(qr + 12);
    const float sc = 0.25f;
    q0.x*=sc;q0.y*=sc;q0.z*=sc;q0.w*=sc; q1.x*=sc;q1.y*=sc;q1.z*=sc;q1.w*=sc;
    q2.x*=sc;q2.y*=sc;q2.z*=sc;q2.w*=sc; q3.x*=sc;q3.y*=sc;q3.z*=sc;q3.w*=sc;

    float t[16];
#pragma unroll
    for (int k = 0; k < 16; k++) t[k] = -3.4e38f;

    // pass 1: top-16 of this thread's half (ascending)
    for (int j = 0; j < LKH; j++) {
        const float4* kj = &sK[(j0 + j) * 4];
        float4 k0 = kj[0], k1 = kj[1], k2 = kj[2], k3 = kj[3];
        float s = q0.x*k0.x + q0.y*k0.y + q0.z*k0.z + q0.w*k0.w
                + q1.x*k1.x + q1.y*k1.y + q1.z*k1.z + q1.w*k1.w
                + q2.x*k2.x + q2.y*k2.y + q2.z*k2.z + q2.w*k2.w
                + q3.x*k3.x + q3.y*k3.y + q3.z*k3.z + q3.w*k3.w;
#pragma unroll
        for (int u = 0; u < 15; u++)
            t[u] = fminf(t[u+1], fmaxf(t[u], s));
        t[15] = fmaxf(t[15], s);
    }

    // exact 16th largest of union via pair shuffles (bitonic selection)
    float thr = 3.4e38f;
#pragma unroll
    for (int i = 0; i < 16; i++) {
        float pt = __shfl_xor_sync(0xffffffffu, t[15 - i], 1);
        thr = fminf(thr, fmaxf(t[i], pt));
    }
    const float m = fmaxf(t[15], __shfl_xor_sync(0xffffffffu, t[15], 1));

    // pass 2: gated accumulate over this thread's half
    float l = 0.f;
    float4 o0 = {0,0,0,0}, o1v = {0,0,0,0}, o2 = {0,0,0,0}, o3 = {0,0,0,0};
    for (int j = 0; j < LKH; j++) {
        const float4* kj = &sK[(j0 + j) * 4];
        float4 k0 = kj[0], k1 = kj[1], k2 = kj[2], k3 = kj[3];
        float s = q0.x*k0.x + q0.y*k0.y + q0.z*k0.z + q0.w*k0.w
                + q1.x*k1.x + q1.y*k1.y + q1.z*k1.z + q1.w*k1.w
                + q2.x*k2.x + q2.y*k2.y + q2.z*k2.z + q2.w*k2.w
                + q3.x*k3.x + q3.y*k3.y + q3.z*k3.z + q3.w*k3.w;
        if (s >= thr) {
            float p = __expf(s - m);
            l += p;
            const float4* vr = reinterpret_cast<const float4*>(vb + (size_t)(j0 + j) * Cc);
            float4 v0 = __ldg(&vr[0]), v1 = __ldg(&vr[1]);
            float4 v2 = __ldg(&vr[2]), v3 = __ldg(&vr[3]);
            o0.x += p*v0.x; o0.y += p*v0.y; o0.z += p*v0.z; o0.w += p*v0.w;
            o1v.x += p*v1.x; o1v.y += p*v1.y; o1v.z += p*v1.z; o1v.w += p*v1.w;
            o2.x += p*v2.x; o2.y += p*v2.y; o2.z += p*v2.z; o2.w += p*v2.w;
            o3.x += p*v3.x; o3.y += p*v3.y; o3.z += p*v3.z; o3.w += p*v3.w;
        }
    }
    // pair combine (shared m -> straight sums)
    l += __shfl_xor_sync(0xffffffffu, l, 1);
    o0.x += __shfl_xor_sync(0xffffffffu, o0.x, 1);
    o0.y += __shfl_xor_sync(0xffffffffu, o0.y, 1);
    o0.z += __shfl_xor_sync(0xffffffffu, o0.z, 1);
    o0.w += __shfl_xor_sync(0xffffffffu, o0.w, 1);
    o1v.x += __shfl_xor_sync(0xffffffffu, o1v.x, 1);
    o1v.y += __shfl_xor_sync(0xffffffffu, o1v.y, 1);
    o1v.z += __shfl_xor_sync(0xffffffffu, o1v.z, 1);
    o1v.w += __shfl_xor_sync(0xffffffffu, o1v.w, 1);
    o2.x += __shfl_xor_sync(0xffffffffu, o2.x, 1);
    o2.y += __shfl_xor_sync(0xffffffffu, o2.y, 1);
    o2.z += __shfl_xor_sync(0xffffffffu, o2.z, 1);
    o2.w += __shfl_xor_sync(0xffffffffu, o2.w, 1);
    o3.x += __shfl_xor_sync(0xffffffffu, o3.x, 1);
    o3.y += __shfl_xor_sync(0xffffffffu, o3.y, 1);
    o3.z += __shfl_xor_sync(0xffffffffu, o3.z, 1);
    o3.w += __shfl_xor_sync(0xffffffffu, o3.w, 1);

    if (half == 0 && qi0 < LQ) {
        float inv = 1.f / l;
        float* orow = att + ((size_t)(b * LQ + qi0)) * Cc + h * 16;
        float4 w0 = {o0.x*inv, o0.y*inv, o0.z*inv, o0.w*inv};
        float4 w1 = {o1v.x*inv, o1v.y*inv, o1v.z*inv, o1v.w*inv};
        float4 w2 = {o2.x*inv, o2.y*inv, o2.z*inv, o2.w*inv};
        float4 w3 = {o3.x*inv, o3.y*inv, o3.z*inv, o3.w*inv};
        *reinterpret_cast<float4*>(orow + 0)  = w0;
        *reinterpret_cast<float4*>(orow + 4)  = w1;
        *reinterpret_cast<float4*>(orow + 8)  = w2;
        *reinterpret_cast<float4*>(orow + 12) = w3;
    }
}

// ---------------- host orchestration ----------------------------------------
extern "C" void kernel_launch(void* const* d_in, const int* in_sizes, int n_in,
                              void* d_out, int out_size)
{
    const float* q        = (const float*)d_in[0];
    const float* enc      = (const float*)d_in[1];
    const float* cal_Wq   = (const float*)d_in[2];
    const float* cal_Wk   = (const float*)d_in[3];
    const float* cal_Wv   = (const float*)d_in[4];
    const float* cal_Wo   = (const float*)d_in[5];
    const float* cal_ln1g = (const float*)d_in[6];
    const float* cal_ln1b = (const float*)d_in[7];
    const float* cal_W1   = (const float*)d_in[8];
    const float* cal_b1   = (const float*)d_in[9];
    const float* cal_W2   = (const float*)d_in[10];
    const float* cal_b2   = (const float*)d_in[11];
    const float* cal_ln2g = (const float*)d_in[12];
    const float* cal_ln2b = (const float*)d_in[13];
    const float* m_ln_g   = (const float*)d_in[14];
    const float* m_ln_b   = (const float*)d_in[15];
    const float* m_fc1_W  = (const float*)d_in[16];
    const float* m_fc1_b  = (const float*)d_in[17];
    const float* m_fc2_W  = (const float*)d_in[18];
    const float* m_fc2_b  = (const float*)d_in[19];
    const float* m_Wq     = (const float*)d_in[20];
    const float* m_Wk     = (const float*)d_in[21];
    const float* m_Wv     = (const float*)d_in[22];
    const float* m_Wo     = (const float*)d_in[23];
    const float* m_aln_g  = (const float*)d_in[24];
    const float* m_aln_b  = (const float*)d_in[25];
    const float* fc_W     = (const float*)d_in[26];
    const float* fc_b     = (const float*)d_in[27];

    float *qp, *kp, *vp, *att, *x, *h1, *x2, *qnA, *qnB, *sg, *xn;
    float *pm, *pl, *po;
    cudaGetSymbolAddress((void**)&qp,  g_qp);
    cudaGetSymbolAddress((void**)&kp,  g_kp);
    cudaGetSymbolAddress((void**)&vp,  g_vp);
    cudaGetSymbolAddress((void**)&att, g_att);
    cudaGetSymbolAddress((void**)&x,   g_x);
    cudaGetSymbolAddress((void**)&h1,  g_h1);
    cudaGetSymbolAddress((void**)&x2,  g_x2);
    cudaGetSymbolAddress((void**)&qnA, g_qnA);
    cudaGetSymbolAddress((void**)&qnB, g_qnB);
    cudaGetSymbolAddress((void**)&sg,  g_sg);
    cudaGetSymbolAddress((void**)&xn,  g_xn);
    cudaGetSymbolAddress((void**)&pm,  g_pm);
    cudaGetSymbolAddress((void**)&pl,  g_pl);
    cudaGetSymbolAddress((void**)&po,  g_po);

    cudaFuncSetAttribute((proj_kernel<64,256,4,1>), cudaFuncAttributeMaxDynamicSharedMemorySize, 65536);
    cudaFuncSetAttribute((gemm_ln_kernel<256>),     cudaFuncAttributeMaxDynamicSharedMemorySize, 65536);
    cudaFuncSetAttribute(attn_topk_fused,           cudaFuncAttributeMaxDynamicSharedMemorySize, 48000);

    const int smem64   = 64 * 64 * 4;           // 16 KB
    const int smemFFN  = 65536;                 // 64 KB
    const int smemAP   = LKH * 64 * 2;          // 48000 B (K+V half)
    const int smemAT   = LKk * 64;              // 48000 B (full K)
    dim3 pgrid((LQ + 255) / 256, Bq * NHh * 2); // (12, 32) plain split
    dim3 tgrid((LQ + 127) / 128, Bq * NHh);     // (24, 16) topk fused
    const int gP = RQ / 32;                     // 375 (exact)
    const int gKV = (RK + 15) / 16;             // 188

    // ---- cross_attn_layer ----
    proj_kernel<64,64,2,0><<<gP, 256, smem64>>>(q, cal_Wq, nullptr, qp, RQ);
    dual_kernel<0,1><<<gKV, 256>>>(enc, cal_Wk, cal_Wv, nullptr, nullptr, kp, vp, RK);
    attn_plain_part<<<pgrid, 256, smemAP>>>(qp, kp, vp, pm, pl, po);
    gemm_ln_attn_kernel<<<gP, 256>>>(pm, pl, po, cal_Wo, q, cal_ln1g, cal_ln1b, x);
    proj_kernel<64,256,4,1><<<RQ/16, 256, smemFFN>>>(x, cal_W1, cal_b1, h1, RQ);
    // FFN2 + LN2 -> x2, fused LN(m_ln[0]) -> qnA
    gemm_ln_kernel<256><<<gP, 256, smemFFN>>>(h1, cal_W2, x, cal_b2,
        cal_ln2g, cal_ln2b, nullptr, nullptr, m_ln_g, m_ln_b, nullptr, nullptr,
        x2, qnA, nullptr, RQ);

    // ---- MGAN decoder layers ----
    float* qncur = qnA;
    float* qnnxt = qnB;
    for (int i = 0; i < 2; i++) {
        dual_kernel<1,2><<<gP, 256>>>(qncur, m_fc1_W + i*4096, m_fc2_W + i*4096,
                                      m_fc1_b + i*64, m_fc2_b + i*64, sg, nullptr, RQ);
        proj_kernel<64,64,2,0><<<gP, 256, smem64>>>(sg, m_Wq + i*4096, nullptr, qp, RQ);
        dual_kernel<0,1><<<gKV, 256>>>(enc, m_Wk + i*4096, m_Wv + i*4096,
                                       nullptr, nullptr, kp, vp, RK);
        attn_topk_fused<<<tgrid, 256, smemAT>>>(qp, kp, vp, att);
        // Wo GEMM + aln LN + GLU; fuse next-layer LN (i==0) or head (i==1)
        if (i == 0) {
            gemm_ln_kernel<64><<<gP, 256, smem64>>>(att, m_Wo + i*4096, sg, nullptr,
                m_aln_g + i*64, m_aln_b + i*64, qncur, sg,
                m_ln_g + 64, m_ln_b + 64, nullptr, nullptr,
                x2, qnnxt, nullptr, RQ);
        } else {
            gemm_ln_kernel<64><<<gP, 256, smem64>>>(att, m_Wo + i*4096, sg, nullptr,
                m_aln_g + i*64, m_aln_b + i*64, qncur, sg,
                nullptr, nullptr, fc_W, fc_b,
                xn, nullptr, (float*)d_out, RQ);
        }
        float* tmp = qncur; qncur = qnnxt; qnnxt = tmp;
    }
}